// round 3
// baseline (speedup 1.0000x reference)
#include <cuda_runtime.h>
#include <cstdint>

#define N_NODES 50000
#define N_EDGES 800000
#define F_IN    128
#define HDIM    128
#define N_HEADS 8
#define HID     16
#define F_OUT   32
#define NEG_SLOPE 0.2f

typedef unsigned long long u64t;

__device__ __forceinline__ void ffma2(u64t& d, u64t a, u64t b) {
    asm("fma.rn.f32x2 %0, %1, %2, %3;" : "=l"(d) : "l"(a), "l"(b), "l"(d));
}
__device__ __forceinline__ u64t dup2(float a) {
    u64t d; asm("mov.b64 %0, {%1, %1};" : "=l"(d) : "f"(a)); return d;
}

// ---------------- device scratch ----------------
__device__ float g_z1[N_NODES * HDIM];
__device__ float g_es1[N_NODES * N_HEADS];
__device__ float g_ed1[N_NODES * N_HEADS];
__device__ float g_h1[N_NODES * HDIM];
__device__ float g_z2[N_NODES * F_OUT];
__device__ float g_es2[N_NODES];
__device__ float g_ed2[N_NODES];
__device__ int   g_deg[N_NODES];
__device__ int   g_rowptr[N_NODES + 1];
__device__ int   g_cursor[N_NODES];
__device__ int   g_csrsrc[N_EDGES];
__device__ int   g_bsum[64];

// ---------------- CSR build ----------------
__global__ void k_hist(const int* __restrict__ dst) {
    int e = blockIdx.x * 256 + threadIdx.x;
    if (e < N_EDGES) atomicAdd(&g_deg[dst[e]], 1);
}

#define SCAN_TPB 256
#define SCAN_ITEMS 8
#define SCAN_TILE 2048
#define SCAN_NTILES ((N_NODES + SCAN_TILE - 1) / SCAN_TILE)   // 25

__global__ void __launch_bounds__(SCAN_TPB) k_scan1() {
    __shared__ int warpsum[8];
    const int t = threadIdx.x;
    const int lane = t & 31, wid = t >> 5;
    const int base = blockIdx.x * SCAN_TILE + t * SCAN_ITEMS;
    int v[SCAN_ITEMS];
    int s = 0;
#pragma unroll
    for (int i = 0; i < SCAN_ITEMS; i++) {
        int idx = base + i;
        v[i] = (idx < N_NODES) ? g_deg[idx] : 0;
        s += v[i];
    }
    int ps = s;
#pragma unroll
    for (int off = 1; off < 32; off <<= 1) {
        int nv = __shfl_up_sync(0xffffffffu, ps, off);
        if (lane >= off) ps += nv;
    }
    if (lane == 31) warpsum[wid] = ps;
    __syncthreads();
    if (wid == 0) {
        int ws = (lane < 8) ? warpsum[lane] : 0;
#pragma unroll
        for (int off = 1; off < 8; off <<= 1) {
            int nv = __shfl_up_sync(0xffffffffu, ws, off);
            if (lane >= off) ws += nv;
        }
        if (lane < 8) warpsum[lane] = ws;
    }
    __syncthreads();
    int excl = ps - s + (wid ? warpsum[wid - 1] : 0);
    int run = excl;
#pragma unroll
    for (int i = 0; i < SCAN_ITEMS; i++) {
        int idx = base + i;
        if (idx < N_NODES) g_rowptr[idx] = run;
        run += v[i];
    }
    if (t == SCAN_TPB - 1) g_bsum[blockIdx.x] = run;
}

__global__ void __launch_bounds__(SCAN_TPB) k_scan2() {
    const int t = threadIdx.x;
    const int lane = t & 31;
    const int b = blockIdx.x;
    int v = (lane < b) ? g_bsum[lane] : 0;
#pragma unroll
    for (int off = 16; off; off >>= 1) v += __shfl_xor_sync(0xffffffffu, v, off);
    const int offn = v;   // sum of g_bsum[0..b)
    const int base = b * SCAN_TILE + t * SCAN_ITEMS;
#pragma unroll
    for (int i = 0; i < SCAN_ITEMS; i++) {
        int idx = base + i;
        if (idx < N_NODES) {
            int r = g_rowptr[idx] + offn;
            g_rowptr[idx] = r;
            g_cursor[idx] = r;
        }
    }
    if (b == 0 && t == 0) g_rowptr[N_NODES] = N_EDGES;
}

__global__ void k_scatter(const int* __restrict__ src, const int* __restrict__ dst) {
    int e = blockIdx.x * 256 + threadIdx.x;
    if (e < N_EDGES) {
        int p = atomicAdd(&g_cursor[dst[e]], 1);
        g_csrsrc[p] = src[e];
    }
}

// ---------------- tiled GEMM (f32x2 FMA) with fused attention-dot epilogue ----------------
// C[M,BN] = A[M,128] @ B[128,BN];  es/ed[n,h] = sum_d C[n, h*HD+d] * avs/avd[h*HD+d]
template <int BN, int TM, int TN, int NH>
__global__ void __launch_bounds__((128 / TM) * (BN / TN))
k_gemm(const float* __restrict__ A, const float* __restrict__ B,
       float* __restrict__ C,
       const float* __restrict__ avs, const float* __restrict__ avd,
       float* __restrict__ esp, float* __restrict__ edp, int M) {
    constexpr int BM = 128, K = 128, PAD = 4;
    constexpr int TX = BN / TN;
    constexpr int NT = (BM / TM) * TX;
    constexpr int HD = BN / NH;       // per-head dim
    constexpr int SL = HD / TN;       // partial slots per (row, head)
    extern __shared__ float smem[];
    float* sA = smem;                    // [K][BM+PAD]
    float* sB = smem + K * (BM + PAD);   // [K][BN]
    const int tid = threadIdx.x;
    const int row0 = blockIdx.x * BM;

    for (int i = tid; i < K * BN; i += NT) sB[i] = B[i];
    for (int i = tid; i < BM * K; i += NT) {
        int k = i & (K - 1);
        int r = i >> 7;
        int row = row0 + r;
        sA[k * (BM + PAD) + r] = (row < M) ? A[(size_t)row * K + k] : 0.f;
    }
    __syncthreads();

    const int tn = (tid % TX) * TN;
    const int tm = (tid / TX) * TM;
    u64t acc[TM][TN / 2];
#pragma unroll
    for (int i = 0; i < TM; i++)
#pragma unroll
        for (int j = 0; j < TN / 2; j++) acc[i][j] = 0ULL;

#pragma unroll 4
    for (int k = 0; k < K; k++) {
        float a[TM];
#pragma unroll
        for (int i = 0; i < TM; i += 4)
            *(float4*)&a[i] = *(const float4*)&sA[k * (BM + PAD) + tm + i];
        u64t b2[TN / 2];
        const u64t* bp = (const u64t*)&sB[k * BN + tn];
#pragma unroll
        for (int j = 0; j < TN / 2; j++) b2[j] = bp[j];
        u64t a2[TM];
#pragma unroll
        for (int i = 0; i < TM; i++) a2[i] = dup2(a[i]);
#pragma unroll
        for (int i = 0; i < TM; i++)
#pragma unroll
            for (int j = 0; j < TN / 2; j++) ffma2(acc[i][j], a2[i], b2[j]);
    }

#pragma unroll
    for (int i = 0; i < TM; i++) {
        int row = row0 + tm + i;
        if (row < M) {
            float* cp = C + (size_t)row * BN + tn;
#pragma unroll
            for (int j = 0; j < TN / 2; j++)
                *(u64t*)&cp[j * 2] = acc[i][j];
        }
    }

    // ---- fused dots epilogue ----
    float* sp_es = smem;                       // [BM][NH][SL]
    float* sp_ed = smem + BM * NH * SL;
    __syncthreads();    // safe to reuse smem

    const int head = tn / HD;
    const int slot = (tn % HD) / TN;
#pragma unroll
    for (int i = 0; i < TM; i++) {
        float pes = 0.f, ped = 0.f;
#pragma unroll
        for (int j = 0; j < TN / 2; j++) {
            float2 v = *(float2*)&acc[i][j];
            int c = head * HD + (tn % HD) + 2 * j;
            pes += v.x * avs[c] + v.y * avs[c + 1];
            ped += v.x * avd[c] + v.y * avd[c + 1];
        }
        sp_es[(tm + i) * NH * SL + head * SL + slot] = pes;
        sp_ed[(tm + i) * NH * SL + head * SL + slot] = ped;
    }
    __syncthreads();
    for (int e = tid; e < BM * NH; e += NT) {
        int row = e / NH, hh = e % NH;
        if (row0 + row < M) {
            float es = 0.f, ed = 0.f;
#pragma unroll
            for (int s2 = 0; s2 < SL; s2++) {
                es += sp_es[row * NH * SL + hh * SL + s2];
                ed += sp_ed[row * NH * SL + hh * SL + s2];
            }
            esp[(size_t)(row0 + row) * NH + hh] = es;
            edp[(size_t)(row0 + row) * NH + hh] = ed;
        }
    }
}

// ---------------- layer1 aggregation: float4 lanes, head = lane>>2 ----------------
__global__ void __launch_bounds__(256) k_agg1() {
    __shared__ int   ss[8][32];
    __shared__ float ws[8][8][33];   // [warp][head][edge]
    const int w = threadIdx.x >> 5;
    const int lane = threadIdx.x & 31;
    const int n = blockIdx.x * 8 + w;
    if (n >= N_NODES) return;
    const int beg = g_rowptr[n], end = g_rowptr[n + 1];
    const int head = lane >> 2;      // lane covers cols [lane*4, lane*4+4) of head
    const int col4 = lane & 31;

    float ed[8];
    {
        float4 lo = *(const float4*)&g_ed1[n * 8];
        float4 hi = *(const float4*)&g_ed1[n * 8 + 4];
        ed[0] = lo.x; ed[1] = lo.y; ed[2] = lo.z; ed[3] = lo.w;
        ed[4] = hi.x; ed[5] = hi.y; ed[6] = hi.z; ed[7] = hi.w;
    }

    float4 acc = make_float4(0.f, 0.f, 0.f, 0.f);
    float ssum[8];
#pragma unroll
    for (int h = 0; h < 8; h++) ssum[h] = 0.f;

    for (int base = beg; base < end; base += 32) {
        const int cnt = min(32, end - base);
        float wv[8];
        int sv = 0;
        if (lane < cnt) {
            sv = g_csrsrc[base + lane];
            float4 lo = *(const float4*)&g_es1[sv * 8];
            float4 hi = *(const float4*)&g_es1[sv * 8 + 4];
            float es[8] = {lo.x, lo.y, lo.z, lo.w, hi.x, hi.y, hi.z, hi.w};
#pragma unroll
            for (int h = 0; h < 8; h++) {
                float t = es[h] + ed[h];
                t = (t >= 0.f) ? t : NEG_SLOPE * t;
                wv[h] = __expf(t);
                ssum[h] += wv[h];
            }
        } else {
#pragma unroll
            for (int h = 0; h < 8; h++) wv[h] = 0.f;
        }
        ss[w][lane] = sv;
#pragma unroll
        for (int h = 0; h < 8; h++) ws[w][h][lane] = wv[h];
        __syncwarp();

        int j = 0;
        for (; j + 4 <= cnt; j += 4) {
#pragma unroll
            for (int u = 0; u < 4; u++) {
                int s = ss[w][j + u];
                float wt = ws[w][head][j + u];
                float4 z = *(const float4*)&g_z1[(size_t)s * HDIM + col4 * 4];
                acc.x += wt * z.x; acc.y += wt * z.y;
                acc.z += wt * z.z; acc.w += wt * z.w;
            }
        }
        for (; j < cnt; j++) {
            int s = ss[w][j];
            float wt = ws[w][head][j];
            float4 z = *(const float4*)&g_z1[(size_t)s * HDIM + col4 * 4];
            acc.x += wt * z.x; acc.y += wt * z.y;
            acc.z += wt * z.z; acc.w += wt * z.w;
        }
        __syncwarp();
    }

#pragma unroll
    for (int h = 0; h < 8; h++)
#pragma unroll
        for (int off = 16; off; off >>= 1)
            ssum[h] += __shfl_xor_sync(0xffffffffu, ssum[h], off);

    float4 r = make_float4(0.f, 0.f, 0.f, 0.f);
    if (end > beg) {
        float inv = 1.f / ssum[head];
        r.x = acc.x * inv; r.y = acc.y * inv;
        r.z = acc.z * inv; r.w = acc.w * inv;
    }
    r.x = (r.x > 0.f) ? r.x : expm1f(r.x);
    r.y = (r.y > 0.f) ? r.y : expm1f(r.y);
    r.z = (r.z > 0.f) ? r.z : expm1f(r.z);
    r.w = (r.w > 0.f) ? r.w : expm1f(r.w);
    *(float4*)&g_h1[(size_t)n * HDIM + col4 * 4] = r;
}

// ---------------- layer2 aggregation: 4 edges x float4 cols per iteration ----------------
__global__ void __launch_bounds__(256) k_agg2(float* __restrict__ out) {
    __shared__ int   ss[8][32];
    __shared__ float ws[8][32];
    const int w = threadIdx.x >> 5;
    const int lane = threadIdx.x & 31;
    const int n = blockIdx.x * 8 + w;
    if (n >= N_NODES) return;
    const int beg = g_rowptr[n], end = g_rowptr[n + 1];
    const float ed = g_ed2[n];
    const int eslot = lane >> 3;   // 0..3
    const int cg = lane & 7;       // col group: cols [cg*4, cg*4+4)
    float4 acc = make_float4(0.f, 0.f, 0.f, 0.f);
    float S = 0.f;

    for (int base = beg; base < end; base += 32) {
        const int cnt = min(32, end - base);
        float wv = 0.f;
        int sv = 0;
        if (lane < cnt) {
            sv = g_csrsrc[base + lane];
            float t = g_es2[sv] + ed;
            t = (t >= 0.f) ? t : NEG_SLOPE * t;
            wv = __expf(t);
            S += wv;
        }
        ss[w][lane] = sv;
        ws[w][lane] = wv;
        __syncwarp();

        for (int j = 0; j < cnt; j += 4) {
            int jj = j + eslot;          // <= 31 always
            int s = ss[w][jj];
            float wt = ws[w][jj];        // 0 beyond cnt
            float4 z = *(const float4*)&g_z2[(size_t)s * F_OUT + cg * 4];
            acc.x += wt * z.x; acc.y += wt * z.y;
            acc.z += wt * z.z; acc.w += wt * z.w;
        }
        __syncwarp();
    }

    // reduce edge slots (xor 8, 16) and softmax sum (full warp)
#pragma unroll
    for (int off = 8; off <= 16; off <<= 1) {
        acc.x += __shfl_xor_sync(0xffffffffu, acc.x, off);
        acc.y += __shfl_xor_sync(0xffffffffu, acc.y, off);
        acc.z += __shfl_xor_sync(0xffffffffu, acc.z, off);
        acc.w += __shfl_xor_sync(0xffffffffu, acc.w, off);
    }
#pragma unroll
    for (int off = 16; off; off >>= 1)
        S += __shfl_xor_sync(0xffffffffu, S, off);

    if (lane < 8) {
        float4 r = make_float4(0.f, 0.f, 0.f, 0.f);
        if (end > beg) {
            float inv = 1.f / S;
            r.x = acc.x * inv; r.y = acc.y * inv;
            r.z = acc.z * inv; r.w = acc.w * inv;
        }
        *(float4*)&out[(size_t)n * F_OUT + lane * 4] = r;
    }
}

// ---------------- launch ----------------
extern "C" void kernel_launch(void* const* d_in, const int* in_sizes, int n_in,
                              void* d_out, int out_size) {
    const float* h   = (const float*)d_in[0];
    const float* W1  = (const float*)d_in[1];
    const float* a1s = (const float*)d_in[2];
    const float* a1d = (const float*)d_in[3];
    const float* W2  = (const float*)d_in[4];
    const float* a2s = (const float*)d_in[5];
    const float* a2d = (const float*)d_in[6];
    const int*   src = (const int*)d_in[7];
    const int*   dst = (const int*)d_in[8];
    float* out = (float*)d_out;

    void *z1p, *h1p, *z2p, *es1p, *ed1p, *es2p, *ed2p, *degp;
    cudaGetSymbolAddress(&z1p, g_z1);
    cudaGetSymbolAddress(&h1p, g_h1);
    cudaGetSymbolAddress(&z2p, g_z2);
    cudaGetSymbolAddress(&es1p, g_es1);
    cudaGetSymbolAddress(&ed1p, g_ed1);
    cudaGetSymbolAddress(&es2p, g_es2);
    cudaGetSymbolAddress(&ed2p, g_ed2);
    cudaGetSymbolAddress(&degp, g_deg);

    constexpr int SM1 = (128 * 132 + 128 * 128) * 4;
    constexpr int SM2 = (128 * 132 + 128 * 32) * 4;
    cudaFuncSetAttribute(k_gemm<128, 8, 8, 8>, cudaFuncAttributeMaxDynamicSharedMemorySize, SM1);
    cudaFuncSetAttribute(k_gemm<32, 8, 4, 1>,  cudaFuncAttributeMaxDynamicSharedMemorySize, SM2);

    const int nb_e = (N_EDGES + 255) / 256;   // 3125
    const int nb_g = (N_NODES + 127) / 128;   // 391
    const int nb_w = (N_NODES + 7) / 8;       // 6250

    cudaMemsetAsync(degp, 0, N_NODES * sizeof(int));
    k_hist<<<nb_e, 256>>>(dst);                          // kernel 0
    k_scan1<<<SCAN_NTILES, SCAN_TPB>>>();                // kernel 1
    k_scan2<<<SCAN_NTILES, SCAN_TPB>>>();                // kernel 2
    k_gemm<128, 8, 8, 8><<<nb_g, 256, SM1>>>(            // kernel 3 (profiled slot)
        h, W1, (float*)z1p, a1s, a1d, (float*)es1p, (float*)ed1p, N_NODES);
    k_scatter<<<nb_e, 256>>>(src, dst);                  // kernel 4
    k_agg1<<<nb_w, 256>>>();                             // kernel 5
    k_gemm<32, 8, 4, 1><<<nb_g, 128, SM2>>>(             // kernel 6
        (const float*)h1p, W2, (float*)z2p, a2s, a2d, (float*)es2p, (float*)ed2p, N_NODES);
    k_agg2<<<nb_w, 256>>>(out);                          // kernel 7
}

// round 4
// speedup vs baseline: 1.8254x; 1.8254x over previous
#include <cuda_runtime.h>
#include <cstdint>

#define N_NODES 50000
#define N_EDGES 800000
#define F_IN    128
#define HDIM    128
#define N_HEADS 8
#define HID     16
#define F_OUT   32
#define NEG_SLOPE 0.2f

typedef unsigned long long u64t;

__device__ __forceinline__ void ffma2(u64t& d, u64t a, u64t b) {
    asm("fma.rn.f32x2 %0, %1, %2, %3;" : "=l"(d) : "l"(a), "l"(b), "l"(d));
}
__device__ __forceinline__ u64t dup2(float a) {
    u64t d; asm("mov.b64 %0, {%1, %1};" : "=l"(d) : "f"(a)); return d;
}

// ---------------- device scratch ----------------
__device__ float g_z1[N_NODES * HDIM];
__device__ float g_es1[N_NODES * N_HEADS];
__device__ float g_ed1[N_NODES * N_HEADS];
__device__ float g_h1[N_NODES * HDIM];
__device__ float g_z2[N_NODES * F_OUT];
__device__ float g_es2[N_NODES];
__device__ float g_ed2[N_NODES];
__device__ int   g_deg[N_NODES];
__device__ int   g_rowptr[N_NODES + 1];
__device__ int   g_cursor[N_NODES];
__device__ int   g_csrsrc[N_EDGES];
__device__ int   g_bsum[64];

// ---------------- CSR build ----------------
__global__ void k_hist(const int* __restrict__ dst) {
    int e = blockIdx.x * 256 + threadIdx.x;
    if (e < N_EDGES) atomicAdd(&g_deg[dst[e]], 1);
}

#define SCAN_TPB 256
#define SCAN_ITEMS 8
#define SCAN_TILE 2048
#define SCAN_NTILES ((N_NODES + SCAN_TILE - 1) / SCAN_TILE)   // 25

__global__ void __launch_bounds__(SCAN_TPB) k_scan1() {
    __shared__ int warpsum[8];
    const int t = threadIdx.x;
    const int lane = t & 31, wid = t >> 5;
    const int base = blockIdx.x * SCAN_TILE + t * SCAN_ITEMS;
    int v[SCAN_ITEMS];
    int s = 0;
#pragma unroll
    for (int i = 0; i < SCAN_ITEMS; i++) {
        int idx = base + i;
        v[i] = (idx < N_NODES) ? g_deg[idx] : 0;
        s += v[i];
    }
    int ps = s;
#pragma unroll
    for (int off = 1; off < 32; off <<= 1) {
        int nv = __shfl_up_sync(0xffffffffu, ps, off);
        if (lane >= off) ps += nv;
    }
    if (lane == 31) warpsum[wid] = ps;
    __syncthreads();
    if (wid == 0) {
        int ws = (lane < 8) ? warpsum[lane] : 0;
#pragma unroll
        for (int off = 1; off < 8; off <<= 1) {
            int nv = __shfl_up_sync(0xffffffffu, ws, off);
            if (lane >= off) ws += nv;
        }
        if (lane < 8) warpsum[lane] = ws;
    }
    __syncthreads();
    int excl = ps - s + (wid ? warpsum[wid - 1] : 0);
    int run = excl;
#pragma unroll
    for (int i = 0; i < SCAN_ITEMS; i++) {
        int idx = base + i;
        if (idx < N_NODES) g_rowptr[idx] = run;
        run += v[i];
    }
    if (t == SCAN_TPB - 1) g_bsum[blockIdx.x] = run;
}

__global__ void __launch_bounds__(SCAN_TPB) k_scan2() {
    const int t = threadIdx.x;
    const int lane = t & 31;
    const int b = blockIdx.x;
    int v = (lane < b) ? g_bsum[lane] : 0;
#pragma unroll
    for (int off = 16; off; off >>= 1) v += __shfl_xor_sync(0xffffffffu, v, off);
    const int offn = v;
    const int base = b * SCAN_TILE + t * SCAN_ITEMS;
#pragma unroll
    for (int i = 0; i < SCAN_ITEMS; i++) {
        int idx = base + i;
        if (idx < N_NODES) {
            int r = g_rowptr[idx] + offn;
            g_rowptr[idx] = r;
            g_cursor[idx] = r;
        }
    }
    if (b == 0 && t == 0) g_rowptr[N_NODES] = N_EDGES;
}

__global__ void k_scatter(const int* __restrict__ src, const int* __restrict__ dst) {
    int e = blockIdx.x * 256 + threadIdx.x;
    if (e < N_EDGES) {
        int p = atomicAdd(&g_cursor[dst[e]], 1);
        g_csrsrc[p] = src[e];
    }
}

// ---------------- double-buffered tiled GEMM (f32x2) + fused attention-dot epilogue ----------------
// C[M,BN] = A[M,128] @ B[128,BN]; es/ed[n,h] = sum_d C[n,h*HD+d]*avs/avd[h*HD+d]
template <int BN, int TM, int TN, int NH, int MINB>
__global__ void __launch_bounds__((128 / TM) * (BN / TN), MINB)
k_gemm(const float* __restrict__ A, const float* __restrict__ B,
       float* __restrict__ C,
       const float* __restrict__ avs, const float* __restrict__ avd,
       float* __restrict__ esp, float* __restrict__ edp, int M) {
    constexpr int BM = 128, K = 128, BK = 16, NK = K / BK, PAD = 4;
    constexpr int TX = BN / TN, TY = BM / TM, NT = TX * TY;
    constexpr int HD = BN / NH;
    constexpr int SL = HD / TN;
    constexpr int LA4 = (BM * BK / 4) / NT;    // float4 A loads per thread
    constexpr int LB4 = (BK * BN / 4) / NT;    // float4 B loads per thread

    __shared__ float sA[2][BK][BM + PAD];
    __shared__ float sB[2][BK][BN];

    const int tid = threadIdx.x;
    const int row0 = blockIdx.x * BM;
    const int tm = (tid / TX) * TM;
    const int tn = (tid % TX) * TN;

    float4 ra[LA4], rb[LB4];

    auto ldg_tile = [&](int kt) {
        const int k0 = kt * BK;
#pragma unroll
        for (int l = 0; l < LA4; l++) {
            int idx = tid + l * NT;
            int r = idx >> 2, cq = idx & 3;
            int row = row0 + r;
            ra[l] = (row < M) ? *(const float4*)&A[(size_t)row * K + k0 + cq * 4]
                              : make_float4(0.f, 0.f, 0.f, 0.f);
        }
#pragma unroll
        for (int l = 0; l < LB4; l++) {
            int idx = tid + l * NT;
            int k = idx / (BN / 4), c4 = idx % (BN / 4);
            rb[l] = *(const float4*)&B[(size_t)(k0 + k) * BN + c4 * 4];
        }
    };
    auto sts_tile = [&](int buf) {
#pragma unroll
        for (int l = 0; l < LA4; l++) {
            int idx = tid + l * NT;
            int r = idx >> 2, cq = idx & 3;
            sA[buf][cq * 4 + 0][r] = ra[l].x;
            sA[buf][cq * 4 + 1][r] = ra[l].y;
            sA[buf][cq * 4 + 2][r] = ra[l].z;
            sA[buf][cq * 4 + 3][r] = ra[l].w;
        }
#pragma unroll
        for (int l = 0; l < LB4; l++) {
            int idx = tid + l * NT;
            int k = idx / (BN / 4), c4 = idx % (BN / 4);
            *(float4*)&sB[buf][k][c4 * 4] = rb[l];
        }
    };

    u64t acc[TM][TN / 2];
#pragma unroll
    for (int i = 0; i < TM; i++)
#pragma unroll
        for (int j = 0; j < TN / 2; j++) acc[i][j] = 0ULL;

    ldg_tile(0);
    sts_tile(0);
    int cur = 0;

    for (int kt = 0; kt < NK; kt++) {
        if (kt + 1 < NK) ldg_tile(kt + 1);
        __syncthreads();
        const float (*pA)[BM + PAD] = sA[cur];
        const float (*pB)[BN] = sB[cur];
#pragma unroll
        for (int k = 0; k < BK; k++) {
            float a[TM];
#pragma unroll
            for (int i = 0; i < TM; i += 4)
                *(float4*)&a[i] = *(const float4*)&pA[k][tm + i];
            u64t b2[TN / 2];
            const u64t* bp = (const u64t*)&pB[k][tn];
#pragma unroll
            for (int j = 0; j < TN / 2; j++) b2[j] = bp[j];
#pragma unroll
            for (int i = 0; i < TM; i++) {
                u64t a2 = dup2(a[i]);
#pragma unroll
                for (int j = 0; j < TN / 2; j++) ffma2(acc[i][j], a2, b2[j]);
            }
        }
        if (kt + 1 < NK) sts_tile(cur ^ 1);
        cur ^= 1;
    }

    // write C
#pragma unroll
    for (int i = 0; i < TM; i++) {
        int row = row0 + tm + i;
        if (row < M) {
            float* cp = C + (size_t)row * BN + tn;
#pragma unroll
            for (int j = 0; j < TN / 2; j++)
                *(u64t*)&cp[j * 2] = acc[i][j];
        }
    }

    // fused attention-dot epilogue (reuse sA as scratch: needs 2*BM*NH*SL floats <= 16.9KB)
    __syncthreads();
    float* sp = (float*)sA;
    const int head = tn / HD;
    const int slot = (tn % HD) / TN;
#pragma unroll
    for (int i = 0; i < TM; i++) {
        float pes = 0.f, ped = 0.f;
#pragma unroll
        for (int j = 0; j < TN / 2; j++) {
            float2 v = *(float2*)&acc[i][j];
            int c = tn + 2 * j;
            pes += v.x * avs[c] + v.y * avs[c + 1];
            ped += v.x * avd[c] + v.y * avd[c + 1];
        }
        sp[((tm + i) * NH + head) * SL + slot] = pes;
        sp[BM * NH * SL + ((tm + i) * NH + head) * SL + slot] = ped;
    }
    __syncthreads();
    for (int e = tid; e < BM * NH; e += NT) {
        int row = e / NH, hh = e % NH;
        if (row0 + row < M) {
            float es = 0.f, ed = 0.f;
#pragma unroll
            for (int s2 = 0; s2 < SL; s2++) {
                es += sp[(row * NH + hh) * SL + s2];
                ed += sp[BM * NH * SL + (row * NH + hh) * SL + s2];
            }
            esp[(size_t)(row0 + row) * NH + hh] = es;
            edp[(size_t)(row0 + row) * NH + hh] = ed;
        }
    }
}

// ---------------- layer1 aggregation: float4 lanes, head = lane>>2 ----------------
__global__ void __launch_bounds__(256) k_agg1() {
    __shared__ int   ss[8][32];
    __shared__ float ws[8][8][33];
    const int w = threadIdx.x >> 5;
    const int lane = threadIdx.x & 31;
    const int n = blockIdx.x * 8 + w;
    if (n >= N_NODES) return;
    const int beg = g_rowptr[n], end = g_rowptr[n + 1];
    const int head = lane >> 2;
    const int col4 = lane & 31;

    float ed[8];
    {
        float4 lo = *(const float4*)&g_ed1[n * 8];
        float4 hi = *(const float4*)&g_ed1[n * 8 + 4];
        ed[0] = lo.x; ed[1] = lo.y; ed[2] = lo.z; ed[3] = lo.w;
        ed[4] = hi.x; ed[5] = hi.y; ed[6] = hi.z; ed[7] = hi.w;
    }

    float4 acc = make_float4(0.f, 0.f, 0.f, 0.f);
    float ssum[8];
#pragma unroll
    for (int h = 0; h < 8; h++) ssum[h] = 0.f;

    for (int base = beg; base < end; base += 32) {
        const int cnt = min(32, end - base);
        float wv[8];
        int sv = 0;
        if (lane < cnt) {
            sv = g_csrsrc[base + lane];
            float4 lo = *(const float4*)&g_es1[sv * 8];
            float4 hi = *(const float4*)&g_es1[sv * 8 + 4];
            float es[8] = {lo.x, lo.y, lo.z, lo.w, hi.x, hi.y, hi.z, hi.w};
#pragma unroll
            for (int h = 0; h < 8; h++) {
                float t = es[h] + ed[h];
                t = (t >= 0.f) ? t : NEG_SLOPE * t;
                wv[h] = __expf(t);
                ssum[h] += wv[h];
            }
        } else {
#pragma unroll
            for (int h = 0; h < 8; h++) wv[h] = 0.f;
        }
        ss[w][lane] = sv;
#pragma unroll
        for (int h = 0; h < 8; h++) ws[w][h][lane] = wv[h];
        __syncwarp();

        int j = 0;
        for (; j + 4 <= cnt; j += 4) {
#pragma unroll
            for (int u = 0; u < 4; u++) {
                int s = ss[w][j + u];
                float wt = ws[w][head][j + u];
                float4 z = *(const float4*)&g_z1[(size_t)s * HDIM + col4 * 4];
                acc.x += wt * z.x; acc.y += wt * z.y;
                acc.z += wt * z.z; acc.w += wt * z.w;
            }
        }
        for (; j < cnt; j++) {
            int s = ss[w][j];
            float wt = ws[w][head][j];
            float4 z = *(const float4*)&g_z1[(size_t)s * HDIM + col4 * 4];
            acc.x += wt * z.x; acc.y += wt * z.y;
            acc.z += wt * z.z; acc.w += wt * z.w;
        }
        __syncwarp();
    }

#pragma unroll
    for (int h = 0; h < 8; h++)
#pragma unroll
        for (int off = 16; off; off >>= 1)
            ssum[h] += __shfl_xor_sync(0xffffffffu, ssum[h], off);

    float4 r = make_float4(0.f, 0.f, 0.f, 0.f);
    if (end > beg) {
        float inv = 1.f / ssum[head];
        r.x = acc.x * inv; r.y = acc.y * inv;
        r.z = acc.z * inv; r.w = acc.w * inv;
    }
    r.x = (r.x > 0.f) ? r.x : expm1f(r.x);
    r.y = (r.y > 0.f) ? r.y : expm1f(r.y);
    r.z = (r.z > 0.f) ? r.z : expm1f(r.z);
    r.w = (r.w > 0.f) ? r.w : expm1f(r.w);
    *(float4*)&g_h1[(size_t)n * HDIM + col4 * 4] = r;
}

// ---------------- layer2 aggregation ----------------
__global__ void __launch_bounds__(256) k_agg2(float* __restrict__ out) {
    __shared__ int   ss[8][32];
    __shared__ float ws[8][32];
    const int w = threadIdx.x >> 5;
    const int lane = threadIdx.x & 31;
    const int n = blockIdx.x * 8 + w;
    if (n >= N_NODES) return;
    const int beg = g_rowptr[n], end = g_rowptr[n + 1];
    const float ed = g_ed2[n];
    const int eslot = lane >> 3;
    const int cg = lane & 7;
    float4 acc = make_float4(0.f, 0.f, 0.f, 0.f);
    float S = 0.f;

    for (int base = beg; base < end; base += 32) {
        const int cnt = min(32, end - base);
        float wv = 0.f;
        int sv = 0;
        if (lane < cnt) {
            sv = g_csrsrc[base + lane];
            float t = g_es2[sv] + ed;
            t = (t >= 0.f) ? t : NEG_SLOPE * t;
            wv = __expf(t);
            S += wv;
        }
        ss[w][lane] = sv;
        ws[w][lane] = wv;
        __syncwarp();

        for (int j = 0; j < cnt; j += 4) {
            int jj = j + eslot;
            int s = ss[w][jj];
            float wt = ws[w][jj];
            float4 z = *(const float4*)&g_z2[(size_t)s * F_OUT + cg * 4];
            acc.x += wt * z.x; acc.y += wt * z.y;
            acc.z += wt * z.z; acc.w += wt * z.w;
        }
        __syncwarp();
    }

#pragma unroll
    for (int off = 8; off <= 16; off <<= 1) {
        acc.x += __shfl_xor_sync(0xffffffffu, acc.x, off);
        acc.y += __shfl_xor_sync(0xffffffffu, acc.y, off);
        acc.z += __shfl_xor_sync(0xffffffffu, acc.z, off);
        acc.w += __shfl_xor_sync(0xffffffffu, acc.w, off);
    }
#pragma unroll
    for (int off = 16; off; off >>= 1)
        S += __shfl_xor_sync(0xffffffffu, S, off);

    if (lane < 8) {
        float4 r = make_float4(0.f, 0.f, 0.f, 0.f);
        if (end > beg) {
            float inv = 1.f / S;
            r.x = acc.x * inv; r.y = acc.y * inv;
            r.z = acc.z * inv; r.w = acc.w * inv;
        }
        *(float4*)&out[(size_t)n * F_OUT + lane * 4] = r;
    }
}

// ---------------- launch ----------------
extern "C" void kernel_launch(void* const* d_in, const int* in_sizes, int n_in,
                              void* d_out, int out_size) {
    const float* h   = (const float*)d_in[0];
    const float* W1  = (const float*)d_in[1];
    const float* a1s = (const float*)d_in[2];
    const float* a1d = (const float*)d_in[3];
    const float* W2  = (const float*)d_in[4];
    const float* a2s = (const float*)d_in[5];
    const float* a2d = (const float*)d_in[6];
    const int*   src = (const int*)d_in[7];
    const int*   dst = (const int*)d_in[8];
    float* out = (float*)d_out;

    void *z1p, *h1p, *z2p, *es1p, *ed1p, *es2p, *ed2p, *degp;
    cudaGetSymbolAddress(&z1p, g_z1);
    cudaGetSymbolAddress(&h1p, g_h1);
    cudaGetSymbolAddress(&z2p, g_z2);
    cudaGetSymbolAddress(&es1p, g_es1);
    cudaGetSymbolAddress(&ed1p, g_ed1);
    cudaGetSymbolAddress(&es2p, g_es2);
    cudaGetSymbolAddress(&ed2p, g_ed2);
    cudaGetSymbolAddress(&degp, g_deg);

    const int nb_e = (N_EDGES + 255) / 256;   // 3125
    const int nb_g = (N_NODES + 127) / 128;   // 391
    const int nb_w = (N_NODES + 7) / 8;       // 6250

    cudaMemsetAsync(degp, 0, N_NODES * sizeof(int));
    k_hist<<<nb_e, 256>>>(dst);
    k_scan1<<<SCAN_NTILES, SCAN_TPB>>>();
    k_scan2<<<SCAN_NTILES, SCAN_TPB>>>();
    k_gemm<128, 8, 8, 8, 2><<<nb_g, 256>>>(
        h, W1, (float*)z1p, a1s, a1d, (float*)es1p, (float*)ed1p, N_NODES);
    k_scatter<<<nb_e, 256>>>(src, dst);
    k_agg1<<<nb_w, 256>>>();
    k_gemm<32, 8, 4, 1, 4><<<nb_g, 128>>>(
        (const float*)h1p, W2, (float*)z2p, a2s, a2d, (float*)es2p, (float*)ed2p, N_NODES);
    k_agg2<<<nb_w, 256>>>(out);
}

// round 5
// speedup vs baseline: 2.2654x; 1.2410x over previous
#include <cuda_runtime.h>
#include <cuda_bf16.h>
#include <cstdint>

#define N_NODES 50000
#define N_EDGES 800000
#define F_IN    128
#define HDIM    128
#define N_HEADS 8
#define HID     16
#define F_OUT   32
#define NEG_SLOPE 0.2f

// ---------------- device scratch ----------------
__device__ float g_z1[N_NODES * HDIM];
__device__ float g_es1[N_NODES * N_HEADS];
__device__ float g_ed1[N_NODES * N_HEADS];
__device__ float g_h1[N_NODES * HDIM];
__device__ float g_z2[N_NODES * F_OUT];
__device__ float g_es2[N_NODES];
__device__ float g_ed2[N_NODES];
__device__ int   g_deg[N_NODES];
__device__ int   g_rowptr[N_NODES + 1];
__device__ int   g_cursor[N_NODES];
__device__ int   g_csrsrc[N_EDGES];
__device__ int   g_bsum[64];

// ---------------- CSR build ----------------
__global__ void k_hist(const int* __restrict__ dst) {
    int e = blockIdx.x * 256 + threadIdx.x;
    if (e < N_EDGES) atomicAdd(&g_deg[dst[e]], 1);
}

#define SCAN_TPB 256
#define SCAN_ITEMS 8
#define SCAN_TILE 2048
#define SCAN_NTILES ((N_NODES + SCAN_TILE - 1) / SCAN_TILE)   // 25

__global__ void __launch_bounds__(SCAN_TPB) k_scan1() {
    __shared__ int warpsum[8];
    const int t = threadIdx.x;
    const int lane = t & 31, wid = t >> 5;
    const int base = blockIdx.x * SCAN_TILE + t * SCAN_ITEMS;
    int v[SCAN_ITEMS];
    int s = 0;
#pragma unroll
    for (int i = 0; i < SCAN_ITEMS; i++) {
        int idx = base + i;
        v[i] = (idx < N_NODES) ? g_deg[idx] : 0;
        s += v[i];
    }
    int ps = s;
#pragma unroll
    for (int off = 1; off < 32; off <<= 1) {
        int nv = __shfl_up_sync(0xffffffffu, ps, off);
        if (lane >= off) ps += nv;
    }
    if (lane == 31) warpsum[wid] = ps;
    __syncthreads();
    if (wid == 0) {
        int ws = (lane < 8) ? warpsum[lane] : 0;
#pragma unroll
        for (int off = 1; off < 8; off <<= 1) {
            int nv = __shfl_up_sync(0xffffffffu, ws, off);
            if (lane >= off) ws += nv;
        }
        if (lane < 8) warpsum[lane] = ws;
    }
    __syncthreads();
    int excl = ps - s + (wid ? warpsum[wid - 1] : 0);
    int run = excl;
#pragma unroll
    for (int i = 0; i < SCAN_ITEMS; i++) {
        int idx = base + i;
        if (idx < N_NODES) g_rowptr[idx] = run;
        run += v[i];
    }
    if (t == SCAN_TPB - 1) g_bsum[blockIdx.x] = run;
}

__global__ void __launch_bounds__(SCAN_TPB) k_scan2() {
    const int t = threadIdx.x;
    const int lane = t & 31;
    const int b = blockIdx.x;
    int v = (lane < b) ? g_bsum[lane] : 0;
#pragma unroll
    for (int off = 16; off; off >>= 1) v += __shfl_xor_sync(0xffffffffu, v, off);
    const int offn = v;
    const int base = b * SCAN_TILE + t * SCAN_ITEMS;
#pragma unroll
    for (int i = 0; i < SCAN_ITEMS; i++) {
        int idx = base + i;
        if (idx < N_NODES) {
            int r = g_rowptr[idx] + offn;
            g_rowptr[idx] = r;
            g_cursor[idx] = r;
        }
    }
    if (b == 0 && t == 0) g_rowptr[N_NODES] = N_EDGES;
}

__global__ void k_scatter(const int* __restrict__ src, const int* __restrict__ dst) {
    int e = blockIdx.x * 256 + threadIdx.x;
    if (e < N_EDGES) {
        int p = atomicAdd(&g_cursor[dst[e]], 1);
        g_csrsrc[p] = src[e];
    }
}

// ---------------- bf16 split-MMA GEMM + fused attention-dot epilogue ----------------
__device__ __forceinline__ void ldsm_x4(uint32_t& r0, uint32_t& r1, uint32_t& r2, uint32_t& r3,
                                        uint32_t addr) {
    asm volatile("ldmatrix.sync.aligned.m8n8.x4.shared.b16 {%0,%1,%2,%3}, [%4];"
                 : "=r"(r0), "=r"(r1), "=r"(r2), "=r"(r3) : "r"(addr));
}
__device__ __forceinline__ void ldsm_x4t(uint32_t& r0, uint32_t& r1, uint32_t& r2, uint32_t& r3,
                                         uint32_t addr) {
    asm volatile("ldmatrix.sync.aligned.m8n8.x4.trans.shared.b16 {%0,%1,%2,%3}, [%4];"
                 : "=r"(r0), "=r"(r1), "=r"(r2), "=r"(r3) : "r"(addr));
}
__device__ __forceinline__ void mma_bf16(float* c, const uint32_t* a, uint32_t b0, uint32_t b1) {
    asm volatile(
        "mma.sync.aligned.m16n8k16.row.col.f32.bf16.bf16.f32 "
        "{%0,%1,%2,%3}, {%4,%5,%6,%7}, {%8,%9}, {%0,%1,%2,%3};"
        : "+f"(c[0]), "+f"(c[1]), "+f"(c[2]), "+f"(c[3])
        : "r"(a[0]), "r"(a[1]), "r"(a[2]), "r"(a[3]), "r"(b0), "r"(b1));
}

__device__ __forceinline__ void cvt_hilo(float x, __nv_bfloat16& h, __nv_bfloat16& l) {
    h = __float2bfloat16(x);
    l = __float2bfloat16(x - __bfloat162float(h));
}

// BN: gemm width; NWARP warps; WC warp-columns; NH heads (HD = BN/NH)
template <int BN, int NWARP, int WC, int NH, int MINB>
__global__ void __launch_bounds__(NWARP * 32, MINB)
k_gemm_tc(const float* __restrict__ A, const float* __restrict__ B,
          float* __restrict__ C,
          const float* __restrict__ avs, const float* __restrict__ avd,
          float* __restrict__ esp, float* __restrict__ edp, int M) {
    constexpr int BM = 128, K = 128, BK = 16, NK = K / BK;
    constexpr int NT = NWARP * 32;
    constexpr int SAS = 24;            // A row stride (bf16 elems): 48B -> conflict-free ldmatrix
    constexpr int BNS = BN + 8;        // B row stride
    constexpr int WR = NWARP / WC;     // warp rows (4)
    constexpr int WTN = BN / WC;       // warp tile cols
    constexpr int NTW = WTN / 8;       // n-tiles per warp
    constexpr int HD = BN / NH;
    constexpr int HWN = WTN / HD;      // heads per warp slice (>=1)
    constexpr int LA4 = (BM * BK / 4) / NT;
    constexpr int LB4 = (BK * BN / 4) / NT;

    __shared__ __nv_bfloat16 sAh[2][BM][SAS];
    __shared__ __nv_bfloat16 sAl[2][BM][SAS];
    __shared__ __nv_bfloat16 sBh[2][BK][BNS];
    __shared__ __nv_bfloat16 sBl[2][BK][BNS];

    const int tid = threadIdx.x;
    const int lane = tid & 31;
    const int wid = tid >> 5;
    const int row0 = blockIdx.x * BM;
    const int tmW = (wid / WC) * (BM / WR);
    const int tnW = (wid % WC) * WTN;

    float4 ra[LA4], rb[LB4];

    auto ldg_tile = [&](int kt) {
        const int k0 = kt * BK;
#pragma unroll
        for (int l = 0; l < LA4; l++) {
            int idx = tid + l * NT;
            int r = idx >> 2, kq = idx & 3;
            int row = row0 + r;
            ra[l] = (row < M) ? *(const float4*)&A[(size_t)row * K + k0 + kq * 4]
                              : make_float4(0.f, 0.f, 0.f, 0.f);
        }
#pragma unroll
        for (int l = 0; l < LB4; l++) {
            int idx = tid + l * NT;
            int k = idx / (BN / 4), nq = idx % (BN / 4);
            rb[l] = *(const float4*)&B[(size_t)(k0 + k) * BN + nq * 4];
        }
    };
    auto sts_tile = [&](int buf) {
#pragma unroll
        for (int l = 0; l < LA4; l++) {
            int idx = tid + l * NT;
            int r = idx >> 2, kq = idx & 3;
            __nv_bfloat16 h0, h1, h2, h3, l0, l1, l2, l3;
            cvt_hilo(ra[l].x, h0, l0); cvt_hilo(ra[l].y, h1, l1);
            cvt_hilo(ra[l].z, h2, l2); cvt_hilo(ra[l].w, h3, l3);
            *(__nv_bfloat162*)&sAh[buf][r][kq * 4]     = __nv_bfloat162(h0, h1);
            *(__nv_bfloat162*)&sAh[buf][r][kq * 4 + 2] = __nv_bfloat162(h2, h3);
            *(__nv_bfloat162*)&sAl[buf][r][kq * 4]     = __nv_bfloat162(l0, l1);
            *(__nv_bfloat162*)&sAl[buf][r][kq * 4 + 2] = __nv_bfloat162(l2, l3);
        }
#pragma unroll
        for (int l = 0; l < LB4; l++) {
            int idx = tid + l * NT;
            int k = idx / (BN / 4), nq = idx % (BN / 4);
            __nv_bfloat16 h0, h1, h2, h3, l0, l1, l2, l3;
            cvt_hilo(rb[l].x, h0, l0); cvt_hilo(rb[l].y, h1, l1);
            cvt_hilo(rb[l].z, h2, l2); cvt_hilo(rb[l].w, h3, l3);
            *(__nv_bfloat162*)&sBh[buf][k][nq * 4]     = __nv_bfloat162(h0, h1);
            *(__nv_bfloat162*)&sBh[buf][k][nq * 4 + 2] = __nv_bfloat162(h2, h3);
            *(__nv_bfloat162*)&sBl[buf][k][nq * 4]     = __nv_bfloat162(l0, l1);
            *(__nv_bfloat162*)&sBl[buf][k][nq * 4 + 2] = __nv_bfloat162(l2, l3);
        }
    };

    float acc[2][NTW][4];
#pragma unroll
    for (int i = 0; i < 2; i++)
#pragma unroll
        for (int j = 0; j < NTW; j++)
#pragma unroll
            for (int q = 0; q < 4; q++) acc[i][j][q] = 0.f;

    ldg_tile(0);
    sts_tile(0);
    int cur = 0;

    // ldmatrix lane-address components
    const int aRow = (lane & 7) + ((lane & 8) ? 8 : 0);
    const int aCol = (lane & 16) ? 8 : 0;
    const int bK = aRow;
    const int bN = aCol;

    for (int kt = 0; kt < NK; kt++) {
        if (kt + 1 < NK) ldg_tile(kt + 1);
        __syncthreads();

        uint32_t ah[2][4], al[2][4];
#pragma unroll
        for (int mt = 0; mt < 2; mt++) {
            int r = tmW + mt * 16 + aRow;
            uint32_t addrh = (uint32_t)__cvta_generic_to_shared(&sAh[cur][r][aCol]);
            uint32_t addrl = (uint32_t)__cvta_generic_to_shared(&sAl[cur][r][aCol]);
            ldsm_x4(ah[mt][0], ah[mt][1], ah[mt][2], ah[mt][3], addrh);
            ldsm_x4(al[mt][0], al[mt][1], al[mt][2], al[mt][3], addrl);
        }
#pragma unroll
        for (int p = 0; p < NTW / 2; p++) {
            int n = tnW + p * 16 + bN;
            uint32_t addrh = (uint32_t)__cvta_generic_to_shared(&sBh[cur][bK][n]);
            uint32_t addrl = (uint32_t)__cvta_generic_to_shared(&sBl[cur][bK][n]);
            uint32_t bh0, bh1, bh2, bh3, bl0, bl1, bl2, bl3;
            ldsm_x4t(bh0, bh1, bh2, bh3, addrh);
            ldsm_x4t(bl0, bl1, bl2, bl3, addrl);
#pragma unroll
            for (int mt = 0; mt < 2; mt++) {
                mma_bf16(acc[mt][2 * p],     ah[mt], bh0, bh1);
                mma_bf16(acc[mt][2 * p],     ah[mt], bl0, bl1);
                mma_bf16(acc[mt][2 * p],     al[mt], bh0, bh1);
                mma_bf16(acc[mt][2 * p + 1], ah[mt], bh2, bh3);
                mma_bf16(acc[mt][2 * p + 1], ah[mt], bl2, bl3);
                mma_bf16(acc[mt][2 * p + 1], al[mt], bh2, bh3);
            }
        }
        if (kt + 1 < NK) sts_tile(cur ^ 1);
        cur ^= 1;
    }

    // ---- write C (float2 per fragment row) ----
    const int cRow = lane >> 2;
    const int cCol = (lane & 3) * 2;
#pragma unroll
    for (int mt = 0; mt < 2; mt++)
#pragma unroll
        for (int nt = 0; nt < NTW; nt++) {
            int col = tnW + nt * 8 + cCol;
            int r1 = row0 + tmW + mt * 16 + cRow;
            int r2 = r1 + 8;
            if (r1 < M) *(float2*)&C[(size_t)r1 * BN + col] = make_float2(acc[mt][nt][0], acc[mt][nt][1]);
            if (r2 < M) *(float2*)&C[(size_t)r2 * BN + col] = make_float2(acc[mt][nt][2], acc[mt][nt][3]);
        }

    // ---- fused attention dots: per (row, head) = sum_col C*av ----
    float pes[2][2][HWN], ped[2][2][HWN];
#pragma unroll
    for (int mt = 0; mt < 2; mt++)
#pragma unroll
        for (int pr = 0; pr < 2; pr++)
#pragma unroll
            for (int hw = 0; hw < HWN; hw++) { pes[mt][pr][hw] = 0.f; ped[mt][pr][hw] = 0.f; }
#pragma unroll
    for (int mt = 0; mt < 2; mt++)
#pragma unroll
        for (int nt = 0; nt < NTW; nt++) {
            int hw = (nt * 8) / HD;
            int c = tnW + nt * 8 + cCol;
            float s0 = avs[c], s1 = avs[c + 1];
            float d0 = avd[c], d1 = avd[c + 1];
            pes[mt][0][hw] += acc[mt][nt][0] * s0 + acc[mt][nt][1] * s1;
            pes[mt][1][hw] += acc[mt][nt][2] * s0 + acc[mt][nt][3] * s1;
            ped[mt][0][hw] += acc[mt][nt][0] * d0 + acc[mt][nt][1] * d1;
            ped[mt][1][hw] += acc[mt][nt][2] * d0 + acc[mt][nt][3] * d1;
        }
#pragma unroll
    for (int mt = 0; mt < 2; mt++)
#pragma unroll
        for (int pr = 0; pr < 2; pr++)
#pragma unroll
            for (int hw = 0; hw < HWN; hw++) {
#pragma unroll
                for (int off = 1; off <= 2; off <<= 1) {
                    pes[mt][pr][hw] += __shfl_xor_sync(0xffffffffu, pes[mt][pr][hw], off);
                    ped[mt][pr][hw] += __shfl_xor_sync(0xffffffffu, ped[mt][pr][hw], off);
                }
            }
    if ((lane & 3) == 0) {
#pragma unroll
        for (int mt = 0; mt < 2; mt++)
#pragma unroll
            for (int pr = 0; pr < 2; pr++) {
                int row = row0 + tmW + mt * 16 + pr * 8 + cRow;
                if (row < M) {
#pragma unroll
                    for (int hw = 0; hw < HWN; hw++) {
                        int hg = tnW / HD + hw;
                        esp[(size_t)row * NH + hg] = pes[mt][pr][hw];
                        edp[(size_t)row * NH + hg] = ped[mt][pr][hw];
                    }
                }
            }
    }
}

// ---------------- layer1 aggregation ----------------
__global__ void __launch_bounds__(256) k_agg1() {
    __shared__ int   ss[8][32];
    __shared__ float ws[8][8][33];
    const int w = threadIdx.x >> 5;
    const int lane = threadIdx.x & 31;
    const int n = blockIdx.x * 8 + w;
    if (n >= N_NODES) return;
    const int beg = g_rowptr[n], end = g_rowptr[n + 1];
    const int head = lane >> 2;
    const int col4 = lane & 31;

    float ed[8];
    {
        float4 lo = *(const float4*)&g_ed1[n * 8];
        float4 hi = *(const float4*)&g_ed1[n * 8 + 4];
        ed[0] = lo.x; ed[1] = lo.y; ed[2] = lo.z; ed[3] = lo.w;
        ed[4] = hi.x; ed[5] = hi.y; ed[6] = hi.z; ed[7] = hi.w;
    }

    float4 acc = make_float4(0.f, 0.f, 0.f, 0.f);
    float ssum[8];
#pragma unroll
    for (int h = 0; h < 8; h++) ssum[h] = 0.f;

    for (int base = beg; base < end; base += 32) {
        const int cnt = min(32, end - base);
        float wv[8];
        int sv = 0;
        if (lane < cnt) {
            sv = g_csrsrc[base + lane];
            float4 lo = *(const float4*)&g_es1[sv * 8];
            float4 hi = *(const float4*)&g_es1[sv * 8 + 4];
            float es[8] = {lo.x, lo.y, lo.z, lo.w, hi.x, hi.y, hi.z, hi.w};
#pragma unroll
            for (int h = 0; h < 8; h++) {
                float t = es[h] + ed[h];
                t = (t >= 0.f) ? t : NEG_SLOPE * t;
                wv[h] = __expf(t);
                ssum[h] += wv[h];
            }
        } else {
#pragma unroll
            for (int h = 0; h < 8; h++) wv[h] = 0.f;
        }
        ss[w][lane] = sv;
#pragma unroll
        for (int h = 0; h < 8; h++) ws[w][h][lane] = wv[h];
        __syncwarp();

        int j = 0;
        for (; j + 4 <= cnt; j += 4) {
#pragma unroll
            for (int u = 0; u < 4; u++) {
                int s = ss[w][j + u];
                float wt = ws[w][head][j + u];
                float4 z = *(const float4*)&g_z1[(size_t)s * HDIM + col4 * 4];
                acc.x += wt * z.x; acc.y += wt * z.y;
                acc.z += wt * z.z; acc.w += wt * z.w;
            }
        }
        for (; j < cnt; j++) {
            int s = ss[w][j];
            float wt = ws[w][head][j];
            float4 z = *(const float4*)&g_z1[(size_t)s * HDIM + col4 * 4];
            acc.x += wt * z.x; acc.y += wt * z.y;
            acc.z += wt * z.z; acc.w += wt * z.w;
        }
        __syncwarp();
    }

#pragma unroll
    for (int h = 0; h < 8; h++)
#pragma unroll
        for (int off = 16; off; off >>= 1)
            ssum[h] += __shfl_xor_sync(0xffffffffu, ssum[h], off);

    float4 r = make_float4(0.f, 0.f, 0.f, 0.f);
    if (end > beg) {
        float inv = 1.f / ssum[head];
        r.x = acc.x * inv; r.y = acc.y * inv;
        r.z = acc.z * inv; r.w = acc.w * inv;
    }
    r.x = (r.x > 0.f) ? r.x : expm1f(r.x);
    r.y = (r.y > 0.f) ? r.y : expm1f(r.y);
    r.z = (r.z > 0.f) ? r.z : expm1f(r.z);
    r.w = (r.w > 0.f) ? r.w : expm1f(r.w);
    *(float4*)&g_h1[(size_t)n * HDIM + col4 * 4] = r;
}

// ---------------- layer2 aggregation ----------------
__global__ void __launch_bounds__(256) k_agg2(float* __restrict__ out) {
    __shared__ int   ss[8][32];
    __shared__ float ws[8][32];
    const int w = threadIdx.x >> 5;
    const int lane = threadIdx.x & 31;
    const int n = blockIdx.x * 8 + w;
    if (n >= N_NODES) return;
    const int beg = g_rowptr[n], end = g_rowptr[n + 1];
    const float ed = g_ed2[n];
    const int eslot = lane >> 3;
    const int cg = lane & 7;
    float4 acc = make_float4(0.f, 0.f, 0.f, 0.f);
    float S = 0.f;

    for (int base = beg; base < end; base += 32) {
        const int cnt = min(32, end - base);
        float wv = 0.f;
        int sv = 0;
        if (lane < cnt) {
            sv = g_csrsrc[base + lane];
            float t = g_es2[sv] + ed;
            t = (t >= 0.f) ? t : NEG_SLOPE * t;
            wv = __expf(t);
            S += wv;
        }
        ss[w][lane] = sv;
        ws[w][lane] = wv;
        __syncwarp();

        for (int j = 0; j < cnt; j += 4) {
            int jj = j + eslot;
            int s = ss[w][jj];
            float wt = ws[w][jj];
            float4 z = *(const float4*)&g_z2[(size_t)s * F_OUT + cg * 4];
            acc.x += wt * z.x; acc.y += wt * z.y;
            acc.z += wt * z.z; acc.w += wt * z.w;
        }
        __syncwarp();
    }

#pragma unroll
    for (int off = 8; off <= 16; off <<= 1) {
        acc.x += __shfl_xor_sync(0xffffffffu, acc.x, off);
        acc.y += __shfl_xor_sync(0xffffffffu, acc.y, off);
        acc.z += __shfl_xor_sync(0xffffffffu, acc.z, off);
        acc.w += __shfl_xor_sync(0xffffffffu, acc.w, off);
    }
#pragma unroll
    for (int off = 16; off; off >>= 1)
        S += __shfl_xor_sync(0xffffffffu, S, off);

    if (lane < 8) {
        float4 r = make_float4(0.f, 0.f, 0.f, 0.f);
        if (end > beg) {
            float inv = 1.f / S;
            r.x = acc.x * inv; r.y = acc.y * inv;
            r.z = acc.z * inv; r.w = acc.w * inv;
        }
        *(float4*)&out[(size_t)n * F_OUT + lane * 4] = r;
    }
}

// ---------------- launch ----------------
extern "C" void kernel_launch(void* const* d_in, const int* in_sizes, int n_in,
                              void* d_out, int out_size) {
    const float* h   = (const float*)d_in[0];
    const float* W1  = (const float*)d_in[1];
    const float* a1s = (const float*)d_in[2];
    const float* a1d = (const float*)d_in[3];
    const float* W2  = (const float*)d_in[4];
    const float* a2s = (const float*)d_in[5];
    const float* a2d = (const float*)d_in[6];
    const int*   src = (const int*)d_in[7];
    const int*   dst = (const int*)d_in[8];
    float* out = (float*)d_out;

    void *z1p, *h1p, *z2p, *es1p, *ed1p, *es2p, *ed2p, *degp;
    cudaGetSymbolAddress(&z1p, g_z1);
    cudaGetSymbolAddress(&h1p, g_h1);
    cudaGetSymbolAddress(&z2p, g_z2);
    cudaGetSymbolAddress(&es1p, g_es1);
    cudaGetSymbolAddress(&ed1p, g_ed1);
    cudaGetSymbolAddress(&es2p, g_es2);
    cudaGetSymbolAddress(&ed2p, g_ed2);
    cudaGetSymbolAddress(&degp, g_deg);

    const int nb_e = (N_EDGES + 255) / 256;   // 3125
    const int nb_g = (N_NODES + 127) / 128;   // 391
    const int nb_w = (N_NODES + 7) / 8;       // 6250

    cudaMemsetAsync(degp, 0, N_NODES * sizeof(int));
    k_hist<<<nb_e, 256>>>(dst);
    k_scan1<<<SCAN_NTILES, SCAN_TPB>>>();
    k_scan2<<<SCAN_NTILES, SCAN_TPB>>>();
    // GEMM1: BN=128, 8 warps (4x2), 8 heads
    k_gemm_tc<128, 8, 2, 8, 2><<<nb_g, 256>>>(
        h, W1, (float*)z1p, a1s, a1d, (float*)es1p, (float*)ed1p, N_NODES);
    k_scatter<<<nb_e, 256>>>(src, dst);
    k_agg1<<<nb_w, 256>>>();
    // GEMM2: BN=32, 4 warps (4x1), 1 head
    k_gemm_tc<32, 4, 1, 1, 4><<<nb_g, 128>>>(
        (const float*)h1p, W2, (float*)z2p, a2s, a2d, (float*)es2p, (float*)ed2p, N_NODES);
    k_agg2<<<nb_w, 256>>>(out);
}